// round 6
// baseline (speedup 1.0000x reference)
#include <cuda_runtime.h>
#include <math_constants.h>

// Problem shape (fixed by the reference):
//   feature_matrix_batch: [S=2, N=32, I=4096, D=128] float32
//   cluster_index:        [S, N*I], int32 OR int64 (JAX x64 off -> int32),
//                         values in [n*K, (n+1)*K) for cloud n
//   output:               [S, N, K=16, D=128] float32 (segment max)

#define SS      2
#define NN      32
#define II      4096
#define DD      128
#define KK      16
#define CHUNKS  16              // split I per cloud -> 1024 blocks total
#define PTS     (II / CHUNKS)   // 256 points per block

// Per-block partial maxima: [S*N*CHUNKS][K*D] = 1024 * 2048 floats = 8 MB
__device__ float g_scratch[SS * NN * CHUNKS * KK * DD];
__device__ int   g_idx_is_64;   // 1 if cluster_index is int64, else int32

// ---------------------------------------------------------------------------
// Dtype detection: indices are in [0, 512). If the buffer is int64, every
// odd 32-bit word (high half) is 0. If int32, odd words are live indices and
// are 0 with probability <= 1/16. Sample 256 pairs, threshold at 128.
// Deterministic, graph-capturable, ~1 us.
// ---------------------------------------------------------------------------
__global__ void detect_idx_dtype(const int* __restrict__ w)
{
    int zeros = 0;
    #pragma unroll 8
    for (int j = 0; j < 256; j++)
        zeros += (w[2 * j + 1] == 0);
    g_idx_is_64 = (zeros > 128);
}

// ---------------------------------------------------------------------------
// Pass 1: each block reduces 256 points of one cloud into a K*D shared tile.
// blockDim = 128: thread x owns feature column x for ALL K segments, so the
// smem update smax[k*128 + x] is race-free without atomics. All global loads
// are fully coalesced (512B per warp-iteration per point-row).
// ---------------------------------------------------------------------------
__global__ void __launch_bounds__(128) maxpool_pass1(
    const float* __restrict__ f,
    const void*  __restrict__ cidx_raw)
{
    const int b     = blockIdx.x;
    const int chunk = b & (CHUNKS - 1);
    const int cloud = b >> 4;            // CHUNKS == 16
    const int n     = cloud & (NN - 1);
    const int s     = cloud >> 5;        // NN == 32
    const int x     = threadIdx.x;

    __shared__ float smax[KK * DD];      // 8 KB
    __shared__ int   soff[PTS];          // precomputed k*D element offsets

    #pragma unroll
    for (int j = 0; j < KK; j++)
        smax[j * DD + x] = -CUDART_INF_F;

    // Stage this chunk's indices into smem -> local segment byte offsets.
    const size_t idx_base = ((size_t)s * NN + n) * II + (size_t)chunk * PTS;
    const int is64 = g_idx_is_64;
    if (is64) {
        const long long* ci = (const long long*)cidx_raw + idx_base;
        for (int j = x; j < PTS; j += 128) {
            int k = (int)ci[j] - n * KK;
            soff[j] = ((unsigned)k < (unsigned)KK) ? k * DD : -1;
        }
    } else {
        const int* ci = (const int*)cidx_raw + idx_base;
        for (int j = x; j < PTS; j += 128) {
            int k = ci[j] - n * KK;
            soff[j] = ((unsigned)k < (unsigned)KK) ? k * DD : -1;
        }
    }
    __syncthreads();

    const float* fp = f + ((size_t)cloud * II + (size_t)chunk * PTS) * DD + x;

    #pragma unroll 8
    for (int i = 0; i < PTS; i++) {
        float v   = fp[(size_t)i * DD];  // coalesced: lane x -> col x
        int   off = soff[i];             // broadcast LDS (same addr per warp)
        if (off >= 0) {
            float cur = smax[off + x];
            smax[off + x] = fmaxf(cur, v);
        }
    }
    __syncthreads();

    float* dst = g_scratch + (size_t)b * (KK * DD);
    #pragma unroll
    for (int j = 0; j < KK; j++)
        dst[j * DD + x] = smax[j * DD + x];
}

// ---------------------------------------------------------------------------
// Pass 2: reduce the 16 chunk-partials per output element. One thread per
// output element; the c-loop strides are identical across a warp, so every
// load is a coalesced 128B line. 8 MB read total -> ~2 us.
// ---------------------------------------------------------------------------
__global__ void __launch_bounds__(256) maxpool_pass2(float* __restrict__ out)
{
    const int t     = blockIdx.x * 256 + threadIdx.x;  // cloud*2048 + (k*128 + d)
    const int cloud = t >> 11;                          // K*D == 2048
    const int j     = t & 2047;

    const float* src = g_scratch + (size_t)cloud * CHUNKS * (KK * DD) + j;
    float m = -CUDART_INF_F;
    #pragma unroll
    for (int c = 0; c < CHUNKS; c++)
        m = fmaxf(m, src[(size_t)c * (KK * DD)]);

    out[t] = m;
}

extern "C" void kernel_launch(void* const* d_in, const int* in_sizes, int n_in,
                              void* d_out, int out_size)
{
    const float* f    = (const float*)d_in[0];   // [2,32,4096,128] f32
    const void*  cidx = d_in[1];                 // [2,131072] i32 or i64
    float*       out  = (float*)d_out;           // [2,32,16,128] f32

    detect_idx_dtype<<<1, 1>>>((const int*)cidx);
    maxpool_pass1<<<SS * NN * CHUNKS, 128>>>(f, cidx);
    maxpool_pass2<<<(SS * NN * KK * DD) / 256, 256>>>(out);
}

// round 7
// speedup vs baseline: 3.5012x; 3.5012x over previous
#include <cuda_runtime.h>
#include <math_constants.h>

// feature_matrix_batch: [S=2, N=32, I=4096, D=128] f32
// cluster_index:        [S, N*I] int32 or int64, values in [n*K,(n+1)*K)
// output:               [S, N, K=16, D=128] f32 segment max (-inf identity)

#define SS      2
#define NN      32
#define II      4096
#define DD      128
#define KK      16
#define CHUNKS  8
#define PTS     (II / CHUNKS)        // 512 points per block
#define NBLK    (SS * NN * CHUNKS)   // 512 blocks
#define ROWF4   32                   // float4 per K-row (128 floats)

// Per-block partials: [512 blocks][16 rows][32 float4] = 4 MB
__device__ float4 g_scratch4[NBLK * KK * ROWF4];

// ---------------------------------------------------------------------------
// Pass 1. 128 threads = 4 warps. Warp w owns points i ≡ w (mod 4) of its
// chunk and a private smem tile smaxw[w][17][32] (row 16 = trash row for
// out-of-range indices -> branch-free hot loop). Lane l owns feature columns
// [4l, 4l+4) for every segment -> no atomics, no cross-thread races.
// All global loads are LDG.128, fully coalesced (512B per warp-instr).
// ---------------------------------------------------------------------------
__global__ void __launch_bounds__(128) maxpool_pass1(
    const float4* __restrict__ f4,
    const int*    __restrict__ cw)    // raw 32-bit view of cluster_index
{
    const int b     = blockIdx.x;
    const int chunk = b & (CHUNKS - 1);
    const int cloud = b >> 3;                 // CHUNKS == 8
    const int n     = cloud & (NN - 1);
    const int x     = threadIdx.x;
    const int w     = x >> 5;
    const int lane  = x & 31;

    __shared__ float4 smaxw[4][KK + 1][ROWF4];  // 34 KB
    __shared__ int    soff[PTS];                // clamped local k, 2 KB

    // dtype sniff: indices < 512, so int64 high words (odd 32-bit words) are
    // all zero; int32 odd words are live k-values (all-zero prob ~2e-10).
    const bool is64 =
        ((cw[1] | cw[3] | cw[5] | cw[7] | cw[9] | cw[11] | cw[13] | cw[15]) == 0);

    // init private tile (incl. trash row 16)
    const float4 neg4 = make_float4(-CUDART_INF_F, -CUDART_INF_F,
                                    -CUDART_INF_F, -CUDART_INF_F);
    #pragma unroll
    for (int r = 0; r <= KK; r++)
        smaxw[w][r][lane] = neg4;

    // stage indices -> clamped local segment id (branch-free consumer)
    const size_t idx_base = (size_t)cloud * II + (size_t)chunk * PTS;
    if (is64) {
        for (int j = x; j < PTS; j += 128) {
            int k = cw[2 * (idx_base + j)] - n * KK;   // low word of int64
            soff[j] = (int)min((unsigned)k, (unsigned)KK);
        }
    } else {
        for (int j = x; j < PTS; j += 128) {
            int k = cw[idx_base + j] - n * KK;
            soff[j] = (int)min((unsigned)k, (unsigned)KK);
        }
    }
    __syncthreads();

    const float4* fp = f4 + ((size_t)cloud * II + (size_t)chunk * PTS) * ROWF4 + lane;
    float4* const my = &smaxw[w][0][lane];      // row stride = ROWF4 float4

    // 128 points per warp, 4 independent point-streams per unrolled group.
    for (int i = w; i < PTS; i += 16) {
        #pragma unroll
        for (int u = 0; u < 4; u++) {
            const int   p = i + 4 * u;
            const float4 v = fp[(size_t)p * ROWF4];   // LDG.128, batched (MLP=4)
            const int   k = soff[p];                  // broadcast LDS
            float4 c = my[k * ROWF4];
            c.x = fmaxf(c.x, v.x);
            c.y = fmaxf(c.y, v.y);
            c.z = fmaxf(c.z, v.z);
            c.w = fmaxf(c.w, v.w);
            my[k * ROWF4] = c;
        }
    }
    __syncthreads();

    // merge the 4 warp-copies (rows 0..15) and write block partial.
    // 512 float4 outputs / 128 threads = 4 each; conflict-free LDS.128.
    float4* dst = g_scratch4 + (size_t)b * (KK * ROWF4);
    #pragma unroll
    for (int q = 0; q < 4; q++) {
        const int idx = x + 128 * q;          // 0..511
        const int r = idx >> 5, l = idx & 31;
        float4 a = smaxw[0][r][l];
        const float4 b1 = smaxw[1][r][l];
        const float4 b2 = smaxw[2][r][l];
        const float4 b3 = smaxw[3][r][l];
        a.x = fmaxf(fmaxf(a.x, b1.x), fmaxf(b2.x, b3.x));
        a.y = fmaxf(fmaxf(a.y, b1.y), fmaxf(b2.y, b3.y));
        a.z = fmaxf(fmaxf(a.z, b1.z), fmaxf(b2.z, b3.z));
        a.w = fmaxf(fmaxf(a.w, b1.w), fmaxf(b2.w, b3.w));
        dst[idx] = a;
    }
}

// ---------------------------------------------------------------------------
// Pass 2: reduce CHUNKS=8 partials per output float4. 4 MB read -> ~1.5 us.
// Warp reads 512B contiguous per chunk-iteration; strides uniform.
// ---------------------------------------------------------------------------
__global__ void __launch_bounds__(256) maxpool_pass2(float4* __restrict__ out4)
{
    const int t     = blockIdx.x * 256 + threadIdx.x;  // cloud*512 + j
    const int cloud = t >> 9;                           // 16*32 = 512 f4/cloud
    const int j     = t & 511;

    const float4* src = g_scratch4 + ((size_t)cloud * CHUNKS) * (KK * ROWF4) + j;
    float4 m = src[0];
    #pragma unroll
    for (int c = 1; c < CHUNKS; c++) {
        const float4 v = src[(size_t)c * (KK * ROWF4)];
        m.x = fmaxf(m.x, v.x);
        m.y = fmaxf(m.y, v.y);
        m.z = fmaxf(m.z, v.z);
        m.w = fmaxf(m.w, v.w);
    }
    out4[t] = m;
}

extern "C" void kernel_launch(void* const* d_in, const int* in_sizes, int n_in,
                              void* d_out, int out_size)
{
    const float4* f4  = (const float4*)d_in[0];
    const int*    cw  = (const int*)d_in[1];
    float4*       out = (float4*)d_out;

    maxpool_pass1<<<NBLK, 128>>>(f4, cw);
    maxpool_pass2<<<(SS * NN * KK * ROWF4) / 256, 256>>>(out);
}

// round 8
// speedup vs baseline: 3.7348x; 1.0667x over previous
#include <cuda_runtime.h>
#include <math_constants.h>

// feature_matrix_batch: [S=2, N=32, I=4096, D=128] f32
// cluster_index:        [S, N*I] int32 or int64, values in [n*K,(n+1)*K)
// output:               [S, N, K=16, D=128] f32 segment max (-inf identity)

#define SS      2
#define NN      32
#define II      4096
#define DD      128
#define KK      16
#define CHUNKS  8
#define PTS     (II / CHUNKS)        // 512 points per block
#define NBLK    (SS * NN * CHUNKS)   // 512 blocks (single wave, 6/SM capacity)
#define ROWF4   32                   // float4 per row (128 floats)
#define TILE    (KK * ROWF4)         // 512 float4 per block partial

// Per-block partials: [512][512 f4] = 4 MB, and per-cloud arrival counters.
__device__ float4 g_scratch4[NBLK * TILE];
__device__ int    g_count[SS * NN];   // zero-init; reset by reducer each run

__global__ void __launch_bounds__(128) maxpool_fused(
    const float4* __restrict__ f4,
    const int*    __restrict__ cw,     // raw 32-bit view of cluster_index
    float4*       __restrict__ out4)
{
    const int b     = blockIdx.x;
    const int chunk = b & (CHUNKS - 1);
    const int cloud = b >> 3;                 // CHUNKS == 8
    const int n     = cloud & (NN - 1);
    const int x     = threadIdx.x;
    const int w     = x >> 5;
    const int lane  = x & 31;

    __shared__ float4 smaxw[4][KK + 1][ROWF4];  // 34 KB (row 16 = trash row)
    __shared__ int    soff[PTS];
    __shared__ int    s_last;

    // dtype sniff: indices < 512 -> int64 high (odd) words all zero.
    const bool is64 =
        ((cw[1] | cw[3] | cw[5] | cw[7] | cw[9] | cw[11] | cw[13] | cw[15]) == 0);

    const float4 neg4 = make_float4(-CUDART_INF_F, -CUDART_INF_F,
                                    -CUDART_INF_F, -CUDART_INF_F);
    #pragma unroll
    for (int r = 0; r <= KK; r++)
        smaxw[w][r][lane] = neg4;

    // Stage indices -> clamped local segment id (branch-free consumer).
    const size_t idx_base = (size_t)cloud * II + (size_t)chunk * PTS;
    if (is64) {
        #pragma unroll
        for (int j = x; j < PTS; j += 128) {
            int k = cw[2 * (idx_base + j)] - n * KK;   // low word of int64
            soff[j] = (int)min((unsigned)k, (unsigned)KK);
        }
    } else {
        #pragma unroll
        for (int j = x; j < PTS; j += 128) {
            int k = cw[idx_base + j] - n * KK;
            soff[j] = (int)min((unsigned)k, (unsigned)KK);
        }
    }
    __syncthreads();

    const float4* fp = f4 + ((size_t)cloud * II + (size_t)chunk * PTS) * ROWF4 + lane;
    float4* const my = &smaxw[w][0][lane];      // row stride = ROWF4 float4

    // ---- DRAM-streaming loop with explicit 1-group register prefetch ----
    // Warp w handles points p = w + 16*g + 4*u (g in [0,32), u in [0,4)).
    float4 v[4];
    int    kk[4];
    #pragma unroll
    for (int u = 0; u < 4; u++) {
        const int p = w + 4 * u;
        v[u]  = fp[p * ROWF4];
        kk[u] = soff[p];
    }
    for (int g = 0; g < 31; g++) {
        float4 vn[4];
        int    kn[4];
        #pragma unroll
        for (int u = 0; u < 4; u++) {          // issue next group's LDG.128s
            const int p = w + 16 * (g + 1) + 4 * u;
            vn[u]  = fp[p * ROWF4];
            kn[u]  = soff[p];
        }
        #pragma unroll
        for (int u = 0; u < 4; u++) {          // smem RMW for current group
            float4 c = my[kk[u] * ROWF4];
            c.x = fmaxf(c.x, v[u].x);
            c.y = fmaxf(c.y, v[u].y);
            c.z = fmaxf(c.z, v[u].z);
            c.w = fmaxf(c.w, v[u].w);
            my[kk[u] * ROWF4] = c;
        }
        #pragma unroll
        for (int u = 0; u < 4; u++) { v[u] = vn[u]; kk[u] = kn[u]; }
    }
    #pragma unroll
    for (int u = 0; u < 4; u++) {              // epilogue group
        float4 c = my[kk[u] * ROWF4];
        c.x = fmaxf(c.x, v[u].x);
        c.y = fmaxf(c.y, v[u].y);
        c.z = fmaxf(c.z, v[u].z);
        c.w = fmaxf(c.w, v[u].w);
        my[kk[u] * ROWF4] = c;
    }
    __syncthreads();

    // ---- merge 4 warp-copies, write block partial ----
    float4* dst = g_scratch4 + (size_t)b * TILE;
    #pragma unroll
    for (int q = 0; q < 4; q++) {
        const int idx = x + 128 * q;           // 0..511
        const int r = idx >> 5, l = idx & 31;
        float4 a = smaxw[0][r][l];
        const float4 b1 = smaxw[1][r][l];
        const float4 b2 = smaxw[2][r][l];
        const float4 b3 = smaxw[3][r][l];
        a.x = fmaxf(fmaxf(a.x, b1.x), fmaxf(b2.x, b3.x));
        a.y = fmaxf(fmaxf(a.y, b1.y), fmaxf(b2.y, b3.y));
        a.z = fmaxf(fmaxf(a.z, b1.z), fmaxf(b2.z, b3.z));
        a.w = fmaxf(fmaxf(a.w, b1.w), fmaxf(b2.w, b3.w));
        dst[idx] = a;
    }

    // ---- last block of each cloud reduces the 8 partials to out ----
    __threadfence();
    __syncthreads();
    if (x == 0)
        s_last = (atomicAdd(&g_count[cloud], 1) == CHUNKS - 1);
    __syncthreads();

    if (s_last) {
        __threadfence();   // acquire-side: order partial reads after counter
        const float4* base = g_scratch4 + (size_t)cloud * CHUNKS * TILE;
        float4*       dout = out4 + (size_t)cloud * TILE;
        #pragma unroll
        for (int q = 0; q < 4; q++) {
            const int idx = x + 128 * q;
            float4 m = base[idx];
            #pragma unroll
            for (int c = 1; c < CHUNKS; c++) {
                const float4 t = base[(size_t)c * TILE + idx];
                m.x = fmaxf(m.x, t.x);
                m.y = fmaxf(m.y, t.y);
                m.z = fmaxf(m.z, t.z);
                m.w = fmaxf(m.w, t.w);
            }
            dout[idx] = m;
        }
        if (x == 0) g_count[cloud] = 0;   // rearm for next graph replay
    }
}

extern "C" void kernel_launch(void* const* d_in, const int* in_sizes, int n_in,
                              void* d_out, int out_size)
{
    const float4* f4  = (const float4*)d_in[0];
    const int*    cw  = (const int*)d_in[1];
    float4*       out = (float4*)d_out;

    maxpool_fused<<<NBLK, 128>>>(f4, cw, out);
}